// round 1
// baseline (speedup 1.0000x reference)
#include <cuda_runtime.h>
#include <math.h>

// Problem constants
#define B_  2
#define S_  2048
#define D_  1024
#define H_  16
#define L_  512
#define DH_ 64
#define NTOK (B_*S_)          // 4096

// ---------------- scratch (device globals: allowed, no allocation) -------------
__device__ float g_c   [NTOK * L_];                     // pre-LN latent      8 MB
__device__ float g_ckv [NTOK * L_];                     // LayerNormed latent 8 MB
__device__ float g_ak  [D_ * L_];                       // absorbed K         2 MB
__device__ float g_tmp [(size_t)B_ * S_ * H_ * L_];     // q_eff [B,S,H,L]  128 MB
__device__ float g_sc  [(size_t)B_ * H_ * S_ * S_];     // scores/attn      512 MB
__device__ float g_v   [NTOK * D_];                     // values            16 MB
__device__ float g_ctx [NTOK * D_];                     // context           16 MB

// ---------------- generic tiled fp32 GEMM --------------------------------------
// C[m,n] = alpha * sum_k A[m,k] * (BT ? B[n,k] : B[k,n])
// Batched over blockIdx.z with (zhi,zlo) = (z/zdiv, z%zdiv) strides.
// CAUSAL: 0 none, 1 skip blocks with n0 > m0+BM-1 (QK^T), 2 clamp K to m0+BM (attn@V).
// Requires: M%BM==0, N%BN==0, K%BK==0 (true for all call sites here).
template<int BM, int BN, int BK, int TM, int TN, bool BT, int CAUSAL>
__global__ __launch_bounds__((BM/TM)*(BN/TN))
void gemm_k(const float* __restrict__ A, const float* __restrict__ B,
            float* __restrict__ C,
            int M, int N, int K, int lda, int ldb, int ldc,
            long sA1, long sA2, long sB1, long sB2, long sC1, long sC2,
            int zdiv, float alpha)
{
    constexpr int THREADS = (BM/TM)*(BN/TN);
    const int z = blockIdx.z;
    const int zhi = z / zdiv, zlo = z % zdiv;
    A += (long)zhi * sA1 + (long)zlo * sA2;
    B += (long)zhi * sB1 + (long)zlo * sB2;
    C += (long)zhi * sC1 + (long)zlo * sC2;

    const int m0 = blockIdx.y * BM;
    const int n0 = blockIdx.x * BN;
    if (CAUSAL == 1 && n0 > m0 + BM - 1) return;
    int Keff = K;
    if (CAUSAL == 2) Keff = min(K, m0 + BM);

    __shared__ float As[BK][BM];
    __shared__ float Bs[BK][BN];

    const int tid  = threadIdx.x;
    const int tcol = tid % (BN/TN);
    const int trow = tid / (BN/TN);

    float acc[TM][TN];
    #pragma unroll
    for (int i = 0; i < TM; i++)
        #pragma unroll
        for (int j = 0; j < TN; j++) acc[i][j] = 0.f;

    constexpr int LA = BM*BK/(4*THREADS);   // float4 loads per thread for A
    constexpr int LB = BN*BK/(4*THREADS);   // float4 loads per thread for B

    for (int k0 = 0; k0 < Keff; k0 += BK) {
        // A tile: K-contiguous loads, transpose into As[k][m]
        #pragma unroll
        for (int i = 0; i < LA; i++) {
            int f   = tid + i*THREADS;
            int row = f / (BK/4);
            int kq  = (f % (BK/4)) * 4;
            float4 v4 = *(const float4*)&A[(long)(m0+row)*lda + k0 + kq];
            As[kq+0][row] = v4.x; As[kq+1][row] = v4.y;
            As[kq+2][row] = v4.z; As[kq+3][row] = v4.w;
        }
        if (BT) {   // B is [N,K], K-contiguous; transpose into Bs[k][n]
            #pragma unroll
            for (int i = 0; i < LB; i++) {
                int f   = tid + i*THREADS;
                int row = f / (BK/4);
                int kq  = (f % (BK/4)) * 4;
                float4 v4 = *(const float4*)&B[(long)(n0+row)*ldb + k0 + kq];
                Bs[kq+0][row] = v4.x; Bs[kq+1][row] = v4.y;
                Bs[kq+2][row] = v4.z; Bs[kq+3][row] = v4.w;
            }
        } else {    // B is [K,N], N-contiguous; direct vector store
            #pragma unroll
            for (int i = 0; i < LB; i++) {
                int f    = tid + i*THREADS;
                int krow = f / (BN/4);
                int nq   = (f % (BN/4)) * 4;
                *(float4*)&Bs[krow][nq] =
                    *(const float4*)&B[(long)(k0+krow)*ldb + n0 + nq];
            }
        }
        __syncthreads();

        #pragma unroll
        for (int k = 0; k < BK; k++) {
            float ar[TM], br[TN];
            #pragma unroll
            for (int i = 0; i < TM; i++) ar[i] = As[k][trow*TM + i];
            #pragma unroll
            for (int j = 0; j < TN; j++) br[j] = Bs[k][tcol*TN + j];
            #pragma unroll
            for (int i = 0; i < TM; i++)
                #pragma unroll
                for (int j = 0; j < TN; j++)
                    acc[i][j] += ar[i] * br[j];
        }
        __syncthreads();
    }

    #pragma unroll
    for (int i = 0; i < TM; i++) {
        long crow = (long)(m0 + trow*TM + i) * ldc + n0 + tcol*TN;
        #pragma unroll
        for (int j = 0; j < TN; j += 4) {
            float4 v4;
            v4.x = acc[i][j+0] * alpha;
            v4.y = acc[i][j+1] * alpha;
            v4.z = acc[i][j+2] * alpha;
            v4.w = acc[i][j+3] * alpha;
            *(float4*)&C[crow + j] = v4;
        }
    }
}

// ---------------- LayerNorm over L=512 ------------------------------------------
__global__ __launch_bounds__(256)
void ln_k(const float* __restrict__ c, float* __restrict__ ckv,
          float* __restrict__ out2,
          const float* __restrict__ gamma, const float* __restrict__ beta)
{
    __shared__ float red[256];
    const int r   = blockIdx.x;            // 0..4095
    const int tid = threadIdx.x;            // 256 threads, 2 elems each
    const float* row = c + (long)r * L_;

    float a0 = row[tid], a1 = row[tid + 256];

    // mean
    red[tid] = a0 + a1; __syncthreads();
    for (int s = 128; s > 0; s >>= 1) { if (tid < s) red[tid] += red[tid+s]; __syncthreads(); }
    float mu = red[0] * (1.0f / L_); __syncthreads();

    float d0 = a0 - mu, d1 = a1 - mu;
    red[tid] = d0*d0 + d1*d1; __syncthreads();
    for (int s = 128; s > 0; s >>= 1) { if (tid < s) red[tid] += red[tid+s]; __syncthreads(); }
    float rstd = rsqrtf(red[0] * (1.0f / L_) + 1e-5f);

    float y0 = d0 * rstd * gamma[tid]       + beta[tid];
    float y1 = d1 * rstd * gamma[tid + 256] + beta[tid + 256];

    long o = (long)r * L_;
    ckv[o + tid] = y0; ckv[o + tid + 256] = y1;
    if (out2) { out2[o + tid] = y0; out2[o + tid + 256] = y1; }
}

// ---------------- causal softmax over t, in place --------------------------------
// Writes softmax for t<=s, zeros for s<t<round_up(s+1,128) (attn@V K-tile boundary).
__global__ __launch_bounds__(256)
void softmax_k(float* __restrict__ sc)
{
    __shared__ float red[256];
    const long r  = blockIdx.x;             // 0 .. B*H*S-1
    const int  s  = (int)(r % S_);
    const int tid = threadIdx.x;
    float* row = sc + r * (long)S_;

    float v[8];
    float mx = -INFINITY;
    #pragma unroll
    for (int i = 0; i < 8; i++) {
        int t = tid + i*256;
        v[i] = (t <= s) ? row[t] : -INFINITY;
        mx = fmaxf(mx, v[i]);
    }
    red[tid] = mx; __syncthreads();
    for (int k = 128; k > 0; k >>= 1) { if (tid < k) red[tid] = fmaxf(red[tid], red[tid+k]); __syncthreads(); }
    mx = red[0]; __syncthreads();

    float sum = 0.f;
    #pragma unroll
    for (int i = 0; i < 8; i++) {
        int t = tid + i*256;
        v[i] = (t <= s) ? __expf(v[i] - mx) : 0.f;
        sum += v[i];
    }
    red[tid] = sum; __syncthreads();
    for (int k = 128; k > 0; k >>= 1) { if (tid < k) red[tid] += red[tid+k]; __syncthreads(); }
    float inv = 1.0f / red[0];

    const int bound = ((s >> 7) + 1) << 7;   // zero-fill through the 128-wide diag tile
    #pragma unroll
    for (int i = 0; i < 8; i++) {
        int t = tid + i*256;
        if (t < bound) row[t] = (t <= s) ? v[i] * inv : 0.f;
    }
}

// ---------------- launch ---------------------------------------------------------
extern "C" void kernel_launch(void* const* d_in, const int* in_sizes, int n_in,
                              void* d_out, int out_size)
{
    const float* x      = (const float*)d_in[0];
    const float* W_q    = (const float*)d_in[1];
    const float* W_dkv  = (const float*)d_in[2];
    const float* W_uk   = (const float*)d_in[3];
    const float* W_uv   = (const float*)d_in[4];
    const float* W_o    = (const float*)d_in[5];
    const float* gamma  = (const float*)d_in[6];
    const float* beta   = (const float*)d_in[7];
    float* out = (float*)d_out;

    float *c, *ckv, *ak, *tmp, *sc, *v, *ctx;
    cudaGetSymbolAddress((void**)&c,   g_c);
    cudaGetSymbolAddress((void**)&ckv, g_ckv);
    cudaGetSymbolAddress((void**)&ak,  g_ak);
    cudaGetSymbolAddress((void**)&tmp, g_tmp);
    cudaGetSymbolAddress((void**)&sc,  g_sc);
    cudaGetSymbolAddress((void**)&v,   g_v);
    cudaGetSymbolAddress((void**)&ctx, g_ctx);

    float* out_ckv = (out_size >= NTOK*D_ + NTOK*L_) ? out + (long)NTOK*D_ : nullptr;

    const dim3 blk(256);

    // K1: c = x @ W_dkv^T   [4096,512] = [4096,1024] @ [512,1024]^T
    gemm_k<128,128,16,8,8,true,0><<<dim3(L_/128, NTOK/128, 1), blk>>>(
        x, W_dkv, c, NTOK, L_, D_, D_, D_, L_,
        0,0, 0,0, 0,0, 16, 1.0f);

    // K2: LayerNorm -> c_kv (and second output)
    ln_k<<<NTOK, 256>>>(c, ckv, out_ckv, gamma, beta);

    // K3: absorbed_k = W_q @ W_uk   [1024,512]
    gemm_k<128,128,16,8,8,false,0><<<dim3(L_/128, D_/128, 1), blk>>>(
        W_q, W_uk, ak, D_, L_, D_, D_, L_, L_,
        0,0, 0,0, 0,0, 16, 1.0f);

    // K4: tmp[b,s,h,:] = x[b,s,h*64:+64] @ ak[h]   (batched over h)
    gemm_k<128,128,16,8,8,false,0><<<dim3(L_/128, NTOK/128, H_), blk>>>(
        x, ak, tmp, NTOK, L_, DH_, D_, L_, H_*L_,
        0, DH_,                  // A: + h*64
        0, (long)DH_*L_,         // B: + h*DH*L
        0, L_,                   // C: + h*L   (tmp is [B,S,H,L])
        16, 1.0f);

    // K5: scores = tmp @ c_kv^T / 8   (batched over b,h; causal block skip)
    gemm_k<128,128,16,8,8,true,1><<<dim3(S_/128, S_/128, B_*H_), blk>>>(
        tmp, ckv, sc, S_, S_, L_, H_*L_, L_, S_,
        (long)S_*H_*L_, (long)L_,            // A: b, h strides
        (long)S_*L_,    0,                   // B: b stride
        (long)H_*S_*S_, (long)S_*S_,         // C: b, h strides
        H_, 0.125f);

    // K6: causal softmax, in place
    softmax_k<<<B_*H_*S_, 256>>>(sc);

    // K7: v = c_kv @ W_uv^T   [4096,1024]
    gemm_k<128,128,16,8,8,true,0><<<dim3(D_/128, NTOK/128, 1), blk>>>(
        ckv, W_uv, v, NTOK, D_, L_, L_, L_, D_,
        0,0, 0,0, 0,0, 16, 1.0f);

    // K8: ctx[b,:,h,:] = attn @ v[b,:,h,:]   (batched over b,h; K clamped causally)
    gemm_k<128,64,16,8,4,false,2><<<dim3(1, S_/128, B_*H_), blk>>>(
        sc, v, ctx, S_, DH_, S_, S_, D_, D_,
        (long)H_*S_*S_, (long)S_*S_,         // A: b, h strides
        (long)S_*D_,    (long)DH_,           // B: b, h strides
        (long)S_*D_,    (long)DH_,           // C: b, h strides
        H_, 1.0f);

    // K9: out = ctx @ W_o^T
    gemm_k<128,128,16,8,8,true,0><<<dim3(D_/128, NTOK/128, 1), blk>>>(
        ctx, W_o, out, NTOK, D_, D_, D_, D_, D_,
        0,0, 0,0, 0,0, 16, 1.0f);
}

// round 2
// speedup vs baseline: 2.2230x; 2.2230x over previous
#include <cuda_runtime.h>
#include <math.h>

// Problem constants
#define B_  2
#define S_  2048
#define D_  1024
#define H_  16
#define L_  512
#define DH_ 64
#define NTOK (B_*S_)          // 4096

// ---------------- scratch (device globals) --------------------------------------
__device__ float g_c   [NTOK * L_];
__device__ float g_ckv [NTOK * L_];
__device__ float g_ak  [D_ * L_];
__device__ float g_tmp [(size_t)B_ * S_ * H_ * L_];
__device__ float g_sc  [(size_t)B_ * H_ * S_ * S_];
__device__ float g_v   [NTOK * D_];
__device__ float g_ctx [NTOK * D_];

// ---------------- tf32 helpers ---------------------------------------------------
__device__ __forceinline__ unsigned f2tf(float f) {
    unsigned u;
    asm("cvt.rna.tf32.f32 %0, %1;" : "=r"(u) : "f"(f));
    return u;
}

__device__ __forceinline__ void mma_tf32(float (&c)[4], const unsigned (&a)[4],
                                         const unsigned (&b)[2]) {
    asm volatile(
        "mma.sync.aligned.m16n8k8.row.col.f32.tf32.tf32.f32 "
        "{%0,%1,%2,%3}, {%4,%5,%6,%7}, {%8,%9}, {%0,%1,%2,%3};"
        : "+f"(c[0]), "+f"(c[1]), "+f"(c[2]), "+f"(c[3])
        : "r"(a[0]), "r"(a[1]), "r"(a[2]), "r"(a[3]), "r"(b[0]), "r"(b[1]));
}

// ---------------- tf32 tensor-core GEMM ------------------------------------------
// C[m,n] = alpha * sum_k A[m,k] * (BT ? B[n,k] : B[k,n])
// 256 threads = 8 warps (2 in M, 4 in N). Warp tile: (BM/2) x (BN/4).
// mma m16n8k8: MT = BM/32 m-tiles, NT = BN/32 n-tiles per warp.
// CAUSAL: 0 none, 1 skip blocks with n0 > m0+BM-1, 2 clamp K to m0+BM.
// Requires: M%BM==0, N%BN==0, K%32==0.
template<int BM, int BN, bool BT, int CAUSAL>
__global__ __launch_bounds__(256, 2)
void mma_gemm(const float* __restrict__ A, const float* __restrict__ B,
              float* __restrict__ C,
              int M, int N, int K, int lda, int ldb, int ldc,
              long sA1, long sA2, long sB1, long sB2, long sC1, long sC2,
              int zdiv, float alpha)
{
    constexpr int BK = 32;
    constexpr int MT = BM / 32;     // m16 tiles per warp (2 warps in M)
    constexpr int NT = BN / 32;     // n8 tiles per warp (4 warps in N)
    constexpr int PAD = 4;

    const int z = blockIdx.z;
    const int zhi = z / zdiv, zlo = z % zdiv;
    A += (long)zhi * sA1 + (long)zlo * sA2;
    B += (long)zhi * sB1 + (long)zlo * sB2;
    C += (long)zhi * sC1 + (long)zlo * sC2;

    const int m0 = blockIdx.y * BM;
    const int n0 = blockIdx.x * BN;
    if (CAUSAL == 1 && n0 > m0 + BM - 1) return;
    int Keff = K;
    if (CAUSAL == 2) Keff = min(K, m0 + BM);

    __shared__ float As[BM][BK + PAD];
    __shared__ float Bs[BK][BN + PAD];

    const int tid  = threadIdx.x;
    const int warp = tid >> 5;
    const int lane = tid & 31;
    const int gid  = lane >> 2;    // 0..7
    const int tig  = lane & 3;     // 0..3
    const int wm0  = (warp & 1) * (BM / 2);
    const int wn0  = (warp >> 1) * (BN / 4);

    float acc[MT][NT][4];
    #pragma unroll
    for (int i = 0; i < MT; i++)
        #pragma unroll
        for (int j = 0; j < NT; j++)
            #pragma unroll
            for (int r = 0; r < 4; r++) acc[i][j][r] = 0.f;

    constexpr int LA = BM * BK / (4 * 256);   // float4 loads/thread for A
    constexpr int LB = BN * BK / (4 * 256);   // float4 loads/thread for B

    for (int k0 = 0; k0 < Keff; k0 += BK) {
        // ---- A tile: row-major [m][k], direct float4 store (no transpose) ----
        #pragma unroll
        for (int i = 0; i < LA; i++) {
            int f   = tid + i * 256;
            int row = f >> 3;              // / (BK/4)
            int kq  = (f & 7) * 4;
            float4 v4 = *(const float4*)&A[(long)(m0 + row) * lda + k0 + kq];
            *(float4*)&As[row][kq] = v4;
        }
        // ---- B tile ----
        if (BT) {   // B is [N,K]: load K-contiguous, transpose into Bs[k][n]
            #pragma unroll
            for (int i = 0; i < LB; i++) {
                int f   = tid + i * 256;
                int row = f >> 3;
                int kq  = (f & 7) * 4;
                float4 v4 = *(const float4*)&B[(long)(n0 + row) * ldb + k0 + kq];
                Bs[kq+0][row] = v4.x; Bs[kq+1][row] = v4.y;
                Bs[kq+2][row] = v4.z; Bs[kq+3][row] = v4.w;
            }
        } else {    // B is [K,N]: direct float4 store
            #pragma unroll
            for (int i = 0; i < LB; i++) {
                int f    = tid + i * 256;
                int krow = f / (BN / 4);
                int nq   = (f % (BN / 4)) * 4;
                *(float4*)&Bs[krow][nq] =
                    *(const float4*)&B[(long)(k0 + krow) * ldb + n0 + nq];
            }
        }
        __syncthreads();

        // ---- 4 k8-steps of mma ----
        #pragma unroll
        for (int ks = 0; ks < 4; ks++) {
            const int kk = ks * 8;
            unsigned a[MT][4];
            #pragma unroll
            for (int mt = 0; mt < MT; mt++) {
                int r = wm0 + mt * 16 + gid;
                a[mt][0] = f2tf(As[r    ][kk + tig    ]);
                a[mt][1] = f2tf(As[r + 8][kk + tig    ]);
                a[mt][2] = f2tf(As[r    ][kk + tig + 4]);
                a[mt][3] = f2tf(As[r + 8][kk + tig + 4]);
            }
            unsigned b[NT][2];
            #pragma unroll
            for (int nt = 0; nt < NT; nt++) {
                int cidx = wn0 + nt * 8 + gid;
                b[nt][0] = f2tf(Bs[kk + tig    ][cidx]);
                b[nt][1] = f2tf(Bs[kk + tig + 4][cidx]);
            }
            #pragma unroll
            for (int mt = 0; mt < MT; mt++)
                #pragma unroll
                for (int nt = 0; nt < NT; nt++)
                    mma_tf32(acc[mt][nt], a[mt], b[nt]);
        }
        __syncthreads();
    }

    // ---- writeback: per mma-tile, thread owns (gid, 2*tig..2*tig+1) & (+8) ----
    #pragma unroll
    for (int mt = 0; mt < MT; mt++) {
        int r0 = m0 + wm0 + mt * 16 + gid;
        #pragma unroll
        for (int nt = 0; nt < NT; nt++) {
            int cc = n0 + wn0 + nt * 8 + tig * 2;
            float2 v0 = make_float2(acc[mt][nt][0] * alpha, acc[mt][nt][1] * alpha);
            float2 v1 = make_float2(acc[mt][nt][2] * alpha, acc[mt][nt][3] * alpha);
            *(float2*)&C[(long)r0 * ldc + cc]       = v0;
            *(float2*)&C[(long)(r0 + 8) * ldc + cc] = v1;
        }
    }
}

// ---------------- LayerNorm over L=512 ------------------------------------------
__global__ __launch_bounds__(256)
void ln_k(const float* __restrict__ c, float* __restrict__ ckv,
          float* __restrict__ out2,
          const float* __restrict__ gamma, const float* __restrict__ beta)
{
    __shared__ float red[256];
    const int r   = blockIdx.x;
    const int tid = threadIdx.x;
    const float* row = c + (long)r * L_;

    float a0 = row[tid], a1 = row[tid + 256];

    red[tid] = a0 + a1; __syncthreads();
    for (int s = 128; s > 0; s >>= 1) { if (tid < s) red[tid] += red[tid+s]; __syncthreads(); }
    float mu = red[0] * (1.0f / L_); __syncthreads();

    float d0 = a0 - mu, d1 = a1 - mu;
    red[tid] = d0*d0 + d1*d1; __syncthreads();
    for (int s = 128; s > 0; s >>= 1) { if (tid < s) red[tid] += red[tid+s]; __syncthreads(); }
    float rstd = rsqrtf(red[0] * (1.0f / L_) + 1e-5f);

    float y0 = d0 * rstd * gamma[tid]       + beta[tid];
    float y1 = d1 * rstd * gamma[tid + 256] + beta[tid + 256];

    long o = (long)r * L_;
    ckv[o + tid] = y0; ckv[o + tid + 256] = y1;
    if (out2) { out2[o + tid] = y0; out2[o + tid + 256] = y1; }
}

// ---------------- causal softmax over t, in place --------------------------------
__global__ __launch_bounds__(256)
void softmax_k(float* __restrict__ sc)
{
    __shared__ float red[256];
    const long r  = blockIdx.x;
    const int  s  = (int)(r % S_);
    const int tid = threadIdx.x;
    float* row = sc + r * (long)S_;

    float v[8];
    float mx = -INFINITY;
    #pragma unroll
    for (int i = 0; i < 8; i++) {
        int t = tid + i*256;
        v[i] = (t <= s) ? row[t] : -INFINITY;
        mx = fmaxf(mx, v[i]);
    }
    red[tid] = mx; __syncthreads();
    for (int k = 128; k > 0; k >>= 1) { if (tid < k) red[tid] = fmaxf(red[tid], red[tid+k]); __syncthreads(); }
    mx = red[0]; __syncthreads();

    float sum = 0.f;
    #pragma unroll
    for (int i = 0; i < 8; i++) {
        int t = tid + i*256;
        v[i] = (t <= s) ? __expf(v[i] - mx) : 0.f;
        sum += v[i];
    }
    red[tid] = sum; __syncthreads();
    for (int k = 128; k > 0; k >>= 1) { if (tid < k) red[tid] += red[tid+k]; __syncthreads(); }
    float inv = 1.0f / red[0];

    const int bound = ((s >> 7) + 1) << 7;   // zero-fill through the 128-wide diag tile
    #pragma unroll
    for (int i = 0; i < 8; i++) {
        int t = tid + i*256;
        if (t < bound) row[t] = (t <= s) ? v[i] * inv : 0.f;
    }
}

// ---------------- launch ---------------------------------------------------------
extern "C" void kernel_launch(void* const* d_in, const int* in_sizes, int n_in,
                              void* d_out, int out_size)
{
    const float* x      = (const float*)d_in[0];
    const float* W_q    = (const float*)d_in[1];
    const float* W_dkv  = (const float*)d_in[2];
    const float* W_uk   = (const float*)d_in[3];
    const float* W_uv   = (const float*)d_in[4];
    const float* W_o    = (const float*)d_in[5];
    const float* gamma  = (const float*)d_in[6];
    const float* beta   = (const float*)d_in[7];
    float* out = (float*)d_out;

    float *c, *ckv, *ak, *tmp, *sc, *v, *ctx;
    cudaGetSymbolAddress((void**)&c,   g_c);
    cudaGetSymbolAddress((void**)&ckv, g_ckv);
    cudaGetSymbolAddress((void**)&ak,  g_ak);
    cudaGetSymbolAddress((void**)&tmp, g_tmp);
    cudaGetSymbolAddress((void**)&sc,  g_sc);
    cudaGetSymbolAddress((void**)&v,   g_v);
    cudaGetSymbolAddress((void**)&ctx, g_ctx);

    float* out_ckv = (out_size >= NTOK*D_ + NTOK*L_) ? out + (long)NTOK*D_ : nullptr;

    const dim3 blk(256);

    // K1: c = x @ W_dkv^T   [4096,512]
    mma_gemm<128,128,true,0><<<dim3(L_/128, NTOK/128, 1), blk>>>(
        x, W_dkv, c, NTOK, L_, D_, D_, D_, L_,
        0,0, 0,0, 0,0, 16, 1.0f);

    // K2: LayerNorm -> c_kv (and second output)
    ln_k<<<NTOK, 256>>>(c, ckv, out_ckv, gamma, beta);

    // K3: absorbed_k = W_q @ W_uk   [1024,512]
    mma_gemm<128,128,false,0><<<dim3(L_/128, D_/128, 1), blk>>>(
        W_q, W_uk, ak, D_, L_, D_, D_, L_, L_,
        0,0, 0,0, 0,0, 16, 1.0f);

    // K4: tmp[b,s,h,:] = x[b,s,h*64:+64] @ ak[h]   (batched over h)
    mma_gemm<128,128,false,0><<<dim3(L_/128, NTOK/128, H_), blk>>>(
        x, ak, tmp, NTOK, L_, DH_, D_, L_, H_*L_,
        0, DH_,
        0, (long)DH_*L_,
        0, L_,
        16, 1.0f);

    // K5: scores = tmp @ c_kv^T / 8   (batched over b,h; causal block skip)
    mma_gemm<128,128,true,1><<<dim3(S_/128, S_/128, B_*H_), blk>>>(
        tmp, ckv, sc, S_, S_, L_, H_*L_, L_, S_,
        (long)S_*H_*L_, (long)L_,
        (long)S_*L_,    0,
        (long)H_*S_*S_, (long)S_*S_,
        H_, 0.125f);

    // K6: causal softmax, in place
    softmax_k<<<B_*H_*S_, 256>>>(sc);

    // K7: v = c_kv @ W_uv^T   [4096,1024]
    mma_gemm<128,128,true,0><<<dim3(D_/128, NTOK/128, 1), blk>>>(
        ckv, W_uv, v, NTOK, D_, L_, L_, L_, D_,
        0,0, 0,0, 0,0, 16, 1.0f);

    // K8: ctx[b,:,h,:] = attn @ v[b,:,h,:]   (batched over b,h; K clamped causally)
    mma_gemm<128,64,false,2><<<dim3(1, S_/128, B_*H_), blk>>>(
        sc, v, ctx, S_, DH_, S_, S_, D_, D_,
        (long)H_*S_*S_, (long)S_*S_,
        (long)S_*D_,    (long)DH_,
        (long)S_*D_,    (long)DH_,
        H_, 1.0f);

    // K9: out = ctx @ W_o^T
    mma_gemm<128,128,true,0><<<dim3(D_/128, NTOK/128, 1), blk>>>(
        ctx, W_o, out, NTOK, D_, D_, D_, D_, D_,
        0,0, 0,0, 0,0, 16, 1.0f);
}